// round 6
// baseline (speedup 1.0000x reference)
#include <cuda_runtime.h>
#include <cuda_bf16.h>
#include <stdint.h>

// x: (n=16, c=256, s=32, h=16, w=11) fp32
// part_labels: (16, 32, 16, 11) int64 (or int32)
// out: (16, 256, 32, 16) fp32
#define N_   16
#define C_   256
#define S_   32
#define HW_  176          // 16*11 = 44 float4 = 22 label-nibble-words
#define P_   16
#define NS_  (N_ * S_)

#define THREADS  128      // 4 warps; thread = channel
#define CGROUPS  2        // 2 channel-groups of 128 -> grid (512, 2)
#define NEG_FILL -100.0f

// accumulate one value into the (sum,max) pair selected by uniform 4-bit label
#define ACC(val, lab) do { float _v = (val); switch (lab) {                    \
    case  0: s0  += _v; m0  = fmaxf(m0 , _v); break;                           \
    case  1: s1  += _v; m1  = fmaxf(m1 , _v); break;                           \
    case  2: s2  += _v; m2  = fmaxf(m2 , _v); break;                           \
    case  3: s3  += _v; m3  = fmaxf(m3 , _v); break;                           \
    case  4: s4  += _v; m4  = fmaxf(m4 , _v); break;                           \
    case  5: s5  += _v; m5  = fmaxf(m5 , _v); break;                           \
    case  6: s6  += _v; m6  = fmaxf(m6 , _v); break;                           \
    case  7: s7  += _v; m7  = fmaxf(m7 , _v); break;                           \
    case  8: s8  += _v; m8  = fmaxf(m8 , _v); break;                           \
    case  9: s9  += _v; m9  = fmaxf(m9 , _v); break;                           \
    case 10: s10 += _v; m10 = fmaxf(m10, _v); break;                           \
    case 11: s11 += _v; m11 = fmaxf(m11, _v); break;                           \
    case 12: s12 += _v; m12 = fmaxf(m12, _v); break;                           \
    case 13: s13 += _v; m13 = fmaxf(m13, _v); break;                           \
    default: s15 += _v; m15 = fmaxf(m15, _v); break;                           \
    case 14: s14 += _v; m14 = fmaxf(m14, _v); break;                           \
} } while (0)

__global__ __launch_bounds__(THREADS)
void hpp_kernel(const float* __restrict__ x,
                const int*   __restrict__ lbl32,
                float*       __restrict__ out)
{
    __shared__ int      s_lbl[HW_];
    __shared__ unsigned s_pk[HW_ / 8];   // 22 words, 8 nibbles each
    __shared__ int      s_cnt[P_];
    __shared__ float    s_inv[P_];
    __shared__ int      s_is64;

    const int ns  = blockIdx.x;
    const int n_i = ns >> 5;
    const int s_i = ns & 31;
    const int tid = threadIdx.x;
    const int c   = blockIdx.y * THREADS + tid;    // this thread's channel

    // ---- prologue: labels -> smem, counts, nibble-pack ----
    if (tid == 0) {
        int allz = 1;
        #pragma unroll
        for (int k = 0; k < 32; k++) allz &= (lbl32[2 * k + 1] == 0);
        s_is64 = allz;
    }
    if (tid < P_) s_cnt[tid] = 0;
    __syncthreads();

    for (int i = tid; i < HW_; i += THREADS) {
        int idx = ns * HW_ + i;
        int l = s_is64 ? lbl32[2 * idx] : lbl32[idx];
        s_lbl[i] = l;
        atomicAdd(&s_cnt[l], 1);
    }
    __syncthreads();

    if (tid < HW_ / 8) {
        unsigned w = 0;
        #pragma unroll
        for (int k = 0; k < 8; k++) w |= ((unsigned)s_lbl[tid * 8 + k]) << (4 * k);
        s_pk[tid] = w;
    }
    if (tid < P_) s_inv[tid] = (s_cnt[tid] > 0) ? (1.0f / (float)s_cnt[tid]) : 0.0f;
    __syncthreads();

    // ---- main: stream own 704B row with LDG.128, uniform-switch accumulate ----
    const float4* r4 = (const float4*)(x + (((size_t)n_i * C_ + c) * S_ + s_i) * HW_);

    float s0=0,s1=0,s2=0,s3=0,s4=0,s5=0,s6=0,s7=0,
          s8=0,s9=0,s10=0,s11=0,s12=0,s13=0,s14=0,s15=0;
    float m0=NEG_FILL,m1=NEG_FILL,m2=NEG_FILL,m3=NEG_FILL,
          m4=NEG_FILL,m5=NEG_FILL,m6=NEG_FILL,m7=NEG_FILL,
          m8=NEG_FILL,m9=NEG_FILL,m10=NEG_FILL,m11=NEG_FILL,
          m12=NEG_FILL,m13=NEG_FILL,m14=NEG_FILL,m15=NEG_FILL;

    // triple-buffered: data for word w+1 and w+2 in flight while processing w
    float4 A0 = r4[0], A1 = r4[1];
    float4 B0 = r4[2], B1 = r4[3];

    #pragma unroll 1
    for (int w = 0; w < HW_ / 8; w++) {
        float4 C0, C1;
        if (w + 2 < HW_ / 8) { C0 = r4[2 * w + 4]; C1 = r4[2 * w + 5]; }
        unsigned lw = s_pk[w];                      // uniform broadcast

        ACC(A0.x,  lw        & 15);
        ACC(A0.y, (lw >>  4) & 15);
        ACC(A0.z, (lw >>  8) & 15);
        ACC(A0.w, (lw >> 12) & 15);
        ACC(A1.x, (lw >> 16) & 15);
        ACC(A1.y, (lw >> 20) & 15);
        ACC(A1.z, (lw >> 24) & 15);
        ACC(A1.w, (lw >> 28) & 15);

        A0 = B0; A1 = B1; B0 = C0; B1 = C1;
    }

    // ---- epilogue: mean + max, zero for empty parts, 4x STG.128 ----
    float r0  = s_cnt[0]  ? s0 * s_inv[0]  + m0  : 0.0f;
    float r1  = s_cnt[1]  ? s1 * s_inv[1]  + m1  : 0.0f;
    float r2  = s_cnt[2]  ? s2 * s_inv[2]  + m2  : 0.0f;
    float r3  = s_cnt[3]  ? s3 * s_inv[3]  + m3  : 0.0f;
    float r4o = s_cnt[4]  ? s4 * s_inv[4]  + m4  : 0.0f;
    float r5  = s_cnt[5]  ? s5 * s_inv[5]  + m5  : 0.0f;
    float r6  = s_cnt[6]  ? s6 * s_inv[6]  + m6  : 0.0f;
    float r7  = s_cnt[7]  ? s7 * s_inv[7]  + m7  : 0.0f;
    float r8  = s_cnt[8]  ? s8 * s_inv[8]  + m8  : 0.0f;
    float r9  = s_cnt[9]  ? s9 * s_inv[9]  + m9  : 0.0f;
    float r10 = s_cnt[10] ? s10 * s_inv[10] + m10 : 0.0f;
    float r11 = s_cnt[11] ? s11 * s_inv[11] + m11 : 0.0f;
    float r12 = s_cnt[12] ? s12 * s_inv[12] + m12 : 0.0f;
    float r13 = s_cnt[13] ? s13 * s_inv[13] + m13 : 0.0f;
    float r14 = s_cnt[14] ? s14 * s_inv[14] + m14 : 0.0f;
    float r15 = s_cnt[15] ? s15 * s_inv[15] + m15 : 0.0f;

    float4* o4 = (float4*)(out + (((size_t)n_i * C_ + c) * S_ + s_i) * P_);
    o4[0] = make_float4(r0,  r1,  r2,  r3);
    o4[1] = make_float4(r4o, r5,  r6,  r7);
    o4[2] = make_float4(r8,  r9,  r10, r11);
    o4[3] = make_float4(r12, r13, r14, r15);
}

extern "C" void kernel_launch(void* const* d_in, const int* in_sizes, int n_in,
                              void* d_out, int out_size)
{
    const float* x    = (const float*)d_in[0];
    const int*   lbls = (const int*)d_in[1];
    float*       out  = (float*)d_out;

    dim3 grid(NS_, CGROUPS);   // 512 x 2, 128 threads
    hpp_kernel<<<grid, THREADS>>>(x, lbls, out);
}

// round 7
// speedup vs baseline: 1.0624x; 1.0624x over previous
#include <cuda_runtime.h>
#include <cuda_bf16.h>
#include <stdint.h>

// x: (n=16, c=256, s=32, h=16, w=11) fp32
// part_labels: (16, 32, 16, 11) int64 (or int32)
// out: (16, 256, 32, 16) fp32
#define N_   16
#define C_   256
#define S_   32
#define HW_  176
#define P_   16
#define NS_  (N_ * S_)

#define THREADS  256
#define CH_PASS  32                 // channels (rows) per pass; lane = row
#define NPASS    (C_ / CH_PASS)     // 8
#define RSTF     208                // row stride in floats (832 B = 52 x 16B)
#define PKW      45                 // packed-index words per part
#define NEG_FILL -100.0f

#define NCH16    (HW_ / 4)          // 44 16B-chunks per row

__device__ __forceinline__ void cpa16(uint32_t dst, const float* src) {
    asm volatile("cp.async.cg.shared.global [%0], [%1], 16;" :: "r"(dst), "l"(src));
}
__device__ __forceinline__ void cpa_commit() {
    asm volatile("cp.async.commit_group;");
}
template<int N> __device__ __forceinline__ void cpa_wait() {
    asm volatile("cp.async.wait_group %0;" :: "n"(N));
}

// skew (in floats) applied to each row's base: keeps gather ~2-way conflict max
__device__ __forceinline__ int rowskew(int row) { return ((row >> 1) & 7) * 4; }

struct SM {
    float    tile[2][CH_PASS * RSTF];  // 53.2 KB double-buffered
    float    res[2][CH_PASS * 17];
    unsigned pk[P_ * PKW];
    int      cnt[P_];
    float    inv[P_];
    int      wcnt[6 * P_];             // per-warp part histograms (warps 0..5)
    unsigned char order[P_];
    int      lbl[HW_];
    int      is64;
};

extern __shared__ char smem_raw[];

// stage one pass's 32 channel rows via 16B cp.async (all 256 threads)
__device__ __forceinline__ void stage_pass(SM* sm, int buf, const float* xbase,
                                           int passCh, int wid, int lane)
{
    float* tb = sm->tile[buf];
    const int rbase = wid * 4;                         // 4 rows per warp
    const float* srcb = xbase + (size_t)(passCh + rbase) * (S_ * HW_);
    #pragma unroll
    for (int k = 0; k < 6; k++) {
        unsigned cidx = (unsigned)(lane + 32 * k);     // 0..175
        if (cidx < 4 * NCH16) {
            unsigned r  = cidx / NCH16;                // row within warp region
            unsigned i16 = cidx - r * NCH16;
            const float* src = srcb + (size_t)r * (S_ * HW_) + i16 * 4;
            float* dstf = tb + (rbase + r) * RSTF + rowskew(rbase + r) + i16 * 4;
            cpa16((uint32_t)__cvta_generic_to_shared(dstf), src);
        }
    }
    cpa_commit();
}

__global__ __launch_bounds__(THREADS)
void hpp_kernel(const float* __restrict__ x,
                const int*   __restrict__ lbl32,
                float*       __restrict__ out)
{
    SM* sm = (SM*)smem_raw;
    const int ns   = blockIdx.x;
    const int n_i  = ns >> 5;
    const int s_i  = ns & 31;
    const int tid  = threadIdx.x;
    const int wid  = tid >> 5;
    const int lane = tid & 31;

    const float* xbase = x + ((size_t)n_i * C_ * S_ + s_i) * HW_;

    // ---- issue first two stages before any prologue work ----
    stage_pass(sm, 0, xbase, 0,        wid, lane);
    stage_pass(sm, 1, xbase, CH_PASS,  wid, lane);

    // ---- prologue ----
    if (tid == 0) {
        int allz = 1;
        #pragma unroll
        for (int k = 0; k < 32; k++) allz &= (lbl32[2 * k + 1] == 0);
        sm->is64 = allz;
    }
    if (tid < 6 * P_) sm->wcnt[tid] = 0;
    __syncthreads();

    int mylbl = -1;
    if (tid < HW_) {
        int idx = ns * HW_ + tid;
        mylbl = sm->is64 ? lbl32[2 * idx] : lbl32[idx];
        sm->lbl[tid] = mylbl;
    }
    __syncthreads();

    // ballot-based stable rank: warps 0..5 hold the 176 label threads
    int rank_in_warp = 0;
    if (tid < HW_) {
        unsigned pmask = (wid == 5) ? 0x0000FFFFu : 0xFFFFFFFFu;
        unsigned mm = __match_any_sync(pmask, mylbl) & pmask;
        rank_in_warp = __popc(mm & ((1u << lane) - 1u));
        if ((mm & ((1u << lane) - 1u)) == 0u)          // leader of this label group
            sm->wcnt[wid * P_ + mylbl] = __popc(mm);
    }
    __syncthreads();

    unsigned char* pkb = (unsigned char*)sm->pk;
    if (tid < HW_) {
        int r = rank_in_warp;
        #pragma unroll
        for (int w = 0; w < 5; w++)
            if (w < wid) r += sm->wcnt[w * P_ + mylbl];
        pkb[mylbl * (PKW * 4) + r] = (unsigned char)tid;
    }
    if (tid >= HW_ && tid < HW_ + P_) {
        int p = tid - HW_;
        int c = 0;
        #pragma unroll
        for (int w = 0; w < 6; w++) c += sm->wcnt[w * P_ + p];
        sm->cnt[p] = c;
        sm->inv[p] = (c > 0) ? (1.0f / (float)c) : 0.0f;
    }
    __syncthreads();

    if (tid < P_) {                                    // pad index lists to /4
        int c = sm->cnt[tid];
        if (c > 0) {
            unsigned char last = pkb[tid * (PKW * 4) + c - 1];
            int e = (c + 3) & ~3;
            for (int j = c; j < e; j++) pkb[tid * (PKW * 4) + j] = last;
        }
    }
    if (tid == 0) {                                    // sort parts by count desc
        unsigned char ord[P_];
        #pragma unroll
        for (int p = 0; p < P_; p++) ord[p] = (unsigned char)p;
        for (int i = 1; i < P_; i++) {
            unsigned char v = ord[i]; int cv = sm->cnt[v]; int j = i - 1;
            while (j >= 0 && sm->cnt[ord[j]] < cv) { ord[j + 1] = ord[j]; j--; }
            ord[j + 1] = v;
        }
        #pragma unroll
        for (int p = 0; p < P_; p++) sm->order[p] = ord[p];
    }
    __syncthreads();

    const int pa = sm->order[wid];
    const int pb = sm->order[15 - wid];

    // ---- pipelined main loop ----
    for (int p = 0; p < NPASS; p++) {
        if (p < NPASS - 1) cpa_wait<1>(); else cpa_wait<0>();
        __syncthreads();

        // write previous pass's results during this pass's window
        if (p > 0) {
            const float* rs = sm->res[(p - 1) & 1];
            const int chb = (p - 1) * CH_PASS;
            #pragma unroll
            for (int k = 0; k < 2; k++) {
                int chl = (tid >> 4) + 16 * k;
                int pp  = tid & 15;
                out[(((size_t)n_i * C_ + (chb + chl)) * S_ + s_i) * P_ + pp]
                    = rs[chl * 17 + pp];
            }
        }

        const float* trow = sm->tile[p & 1] + lane * RSTF + rowskew(lane);
        float* rbuf = sm->res[p & 1];

        #pragma unroll
        for (int pi = 0; pi < 2; pi++) {
            const int pp = pi ? pb : pa;
            const int c = sm->cnt[pp];
            float r = 0.0f;
            if (c > 0) {
                const int W   = (c + 3) >> 2;
                const int pad = (W << 2) - c;
                const unsigned* pk = &sm->pk[pp * PKW];
                float sum = 0.0f, mx = NEG_FILL;
                for (int w = 0; w < W; w++) {
                    unsigned iw = pk[w];                // uniform broadcast
                    float v0 = trow[iw & 255];
                    float v1 = trow[(iw >> 8) & 255];
                    float v2 = trow[(iw >> 16) & 255];
                    float v3 = trow[iw >> 24];
                    sum += (v0 + v1) + (v2 + v3);
                    mx = fmaxf(fmaxf(v0, v1), fmaxf(fmaxf(v2, v3), mx));
                }
                if (pad) sum -= (float)pad * trow[pkb[pp * (PKW * 4) + c - 1]];
                r = sum * sm->inv[pp] + mx;
            }
            rbuf[lane * 17 + pp] = r;
        }
        __syncthreads();

        if (p + 2 < NPASS)
            stage_pass(sm, p & 1, xbase, (p + 2) * CH_PASS, wid, lane);
    }

    // final pass's results
    {
        const float* rs = sm->res[(NPASS - 1) & 1];
        const int chb = (NPASS - 1) * CH_PASS;
        #pragma unroll
        for (int k = 0; k < 2; k++) {
            int chl = (tid >> 4) + 16 * k;
            int pp  = tid & 15;
            out[(((size_t)n_i * C_ + (chb + chl)) * S_ + s_i) * P_ + pp]
                = rs[chl * 17 + pp];
        }
    }
}

extern "C" void kernel_launch(void* const* d_in, const int* in_sizes, int n_in,
                              void* d_out, int out_size)
{
    const float* x    = (const float*)d_in[0];
    const int*   lbls = (const int*)d_in[1];
    float*       out  = (float*)d_out;

    cudaFuncSetAttribute(hpp_kernel, cudaFuncAttributeMaxDynamicSharedMemorySize,
                         (int)sizeof(SM));
    hpp_kernel<<<NS_, THREADS, sizeof(SM)>>>(x, lbls, out);
}

// round 9
// speedup vs baseline: 1.0991x; 1.0346x over previous
#include <cuda_runtime.h>
#include <cuda_bf16.h>
#include <stdint.h>

// x: (n=16, c=256, s=32, h=16, w=11) fp32
// part_labels: (16, 32, 16, 11) int64 (or int32)
// out: (16, 256, 32, 16) fp32
#define N_   16
#define C_   256
#define S_   32
#define HW_  176
#define P_   16
#define NS_  (N_ * S_)

#define THREADS  256
#define CH_PASS  32                 // channels (rows) per pass; lane = row
#define NPASS    (C_ / CH_PASS)     // 8
#define RSTF     177                // odd stride -> conflict-free gather
#define PKW      45
#define NEG_FILL -100.0f
#define CHUNKS   (4 * (HW_ / 4))    // 176 16B-chunks per 4-row warp region

struct SM {
    float    tile[2][CH_PASS * RSTF];   // 45.3 KB
    float    res[2][CH_PASS * 17];
    unsigned pk[P_ * PKW];
    int      cnt[P_];
    float    inv[P_];
    int      wcnt[6 * P_];
    unsigned char order[P_];
    int      is64;
};

extern __shared__ char smem_raw[];

// load one pass's warp-region (4 rows x 44 float4) into registers
__device__ __forceinline__ void ldg_pass(float4 v[6], const float* __restrict__ xbase,
                                         int passCh, int wid, int lane)
{
    const float* src = xbase + (size_t)(passCh + wid * 4) * (S_ * HW_);
    #pragma unroll
    for (int k = 0; k < 6; k++) {
        int cid = k * 32 + lane;            // 0..191, active < 176
        if (cid < CHUNKS) {
            int row = cid / 44;
            int c   = cid - row * 44;
            v[k] = *(const float4*)(src + (size_t)row * (S_ * HW_) + c * 4);
        } else {
            v[k] = make_float4(0.f, 0.f, 0.f, 0.f);
        }
    }
}

// store registers to the smem tile (odd row stride: 4 x STS.32 per chunk)
__device__ __forceinline__ void sts_pass(float* __restrict__ tile, const float4 v[6],
                                         int wid, int lane)
{
    #pragma unroll
    for (int k = 0; k < 6; k++) {
        int cid = k * 32 + lane;
        if (cid < CHUNKS) {
            int row = cid / 44;
            int c   = cid - row * 44;
            float* d = tile + (wid * 4 + row) * RSTF + c * 4;
            d[0] = v[k].x; d[1] = v[k].y; d[2] = v[k].z; d[3] = v[k].w;
        }
    }
}

__global__ __launch_bounds__(THREADS)
void hpp_kernel(const float* __restrict__ x,
                const int*   __restrict__ lbl32,
                float*       __restrict__ out)
{
    SM* sm = (SM*)smem_raw;
    const int ns   = blockIdx.x;
    const int n_i  = ns >> 5;
    const int s_i  = ns & 31;
    const int tid  = threadIdx.x;
    const int wid  = tid >> 5;
    const int lane = tid & 31;

    const float* xbase = x + ((size_t)n_i * C_ * S_ + s_i) * HW_;

    // ---- deepest prefetch first: passes 0 and 1 into registers ----
    float4 v0[6], v1[6];
    ldg_pass(v0, xbase, 0,        wid, lane);
    ldg_pass(v1, xbase, CH_PASS,  wid, lane);

    // ---- label prologue (overlaps LDG flight) ----
    if (tid == 0) {
        int allz = 1;
        #pragma unroll
        for (int k = 0; k < 32; k++) allz &= (lbl32[2 * k + 1] == 0);
        sm->is64 = allz;
    }
    if (tid < 6 * P_) sm->wcnt[tid] = 0;
    __syncthreads();

    int mylbl = -1;
    if (tid < HW_) {
        int idx = ns * HW_ + tid;
        mylbl = sm->is64 ? lbl32[2 * idx] : lbl32[idx];
    }
    __syncthreads();

    int rank_in_warp = 0;
    if (tid < HW_) {
        unsigned pmask = (wid == 5) ? 0x0000FFFFu : 0xFFFFFFFFu;
        unsigned mm = __match_any_sync(pmask, mylbl) & pmask;
        rank_in_warp = __popc(mm & ((1u << lane) - 1u));
        if ((mm & ((1u << lane) - 1u)) == 0u)
            sm->wcnt[wid * P_ + mylbl] = __popc(mm);
    }
    __syncthreads();

    unsigned char* pkb = (unsigned char*)sm->pk;
    if (tid < HW_) {
        int r = rank_in_warp;
        #pragma unroll
        for (int w = 0; w < 5; w++)
            if (w < wid) r += sm->wcnt[w * P_ + mylbl];
        pkb[mylbl * (PKW * 4) + r] = (unsigned char)tid;
    }
    if (tid >= HW_ && tid < HW_ + P_) {
        int p = tid - HW_;
        int c = 0;
        #pragma unroll
        for (int w = 0; w < 6; w++) c += sm->wcnt[w * P_ + p];
        sm->cnt[p] = c;
        sm->inv[p] = (c > 0) ? (1.0f / (float)c) : 0.0f;
    }
    __syncthreads();

    if (tid < P_) {
        int c = sm->cnt[tid];
        if (c > 0) {
            unsigned char last = pkb[tid * (PKW * 4) + c - 1];
            int e = (c + 3) & ~3;
            for (int j = c; j < e; j++) pkb[tid * (PKW * 4) + j] = last;
        }
    }
    if (tid == 0) {
        unsigned char ord[P_];
        #pragma unroll
        for (int p = 0; p < P_; p++) ord[p] = (unsigned char)p;
        for (int i = 1; i < P_; i++) {
            unsigned char vv = ord[i]; int cv = sm->cnt[vv]; int j = i - 1;
            while (j >= 0 && sm->cnt[ord[j]] < cv) { ord[j + 1] = ord[j]; j--; }
            ord[j + 1] = vv;
        }
        #pragma unroll
        for (int p = 0; p < P_; p++) sm->order[p] = ord[p];
    }

    // stage pass 0 into buf0, refill v0 with pass 2
    sts_pass(sm->tile[0], v0, wid, lane);
    ldg_pass(v0, xbase, 2 * CH_PASS, wid, lane);
    __syncthreads();

    const int pa = sm->order[wid];
    const int pb = sm->order[15 - wid];

    // ---- main loop: one barrier per pass ----
    // invariant at top of iter p: buf[p&1] holds pass p; v[(p+1)&1] holds pass p+1
    for (int p = 0; p < NPASS; p++) {
        // stage p+1 (disjoint buffer from the one being gathered)
        if (p + 1 < NPASS) {
            if (((p + 1) & 1) == 0) sts_pass(sm->tile[0], v0, wid, lane);
            else                    sts_pass(sm->tile[1], v1, wid, lane);
        }
        // refill the just-consumed register set with pass p+3
        if (p + 3 < NPASS) {
            if (((p + 1) & 1) == 0) ldg_pass(v0, xbase, (p + 3) * CH_PASS, wid, lane);
            else                    ldg_pass(v1, xbase, (p + 3) * CH_PASS, wid, lane);
        }

        // write previous pass's results (coalesced via smem transpose)
        if (p > 0) {
            const float* rs = sm->res[(p - 1) & 1];
            const int chb = (p - 1) * CH_PASS;
            #pragma unroll
            for (int k = 0; k < 2; k++) {
                int chl = (tid >> 4) + 16 * k;
                int pp  = tid & 15;
                out[(((size_t)n_i * C_ + (chb + chl)) * S_ + s_i) * P_ + pp]
                    = rs[chl * 17 + pp];
            }
        }

        // gather pass p: lane = row, uniform part index -> conflict-free
        const float* trow = sm->tile[p & 1] + lane * RSTF;
        float* rbuf = sm->res[p & 1];

        #pragma unroll
        for (int pi = 0; pi < 2; pi++) {
            const int pp = pi ? pb : pa;
            const int c = sm->cnt[pp];
            float r = 0.0f;
            if (c > 0) {
                const int W   = (c + 3) >> 2;
                const int pad = (W << 2) - c;
                const unsigned* __restrict__ pk = &sm->pk[pp * PKW];
                float sum = 0.0f, mx = NEG_FILL;
                for (int w = 0; w < W; w++) {
                    unsigned iw = pk[w];
                    float a0 = trow[iw & 255];
                    float a1 = trow[(iw >> 8) & 255];
                    float a2 = trow[(iw >> 16) & 255];
                    float a3 = trow[iw >> 24];
                    sum += (a0 + a1) + (a2 + a3);
                    mx = fmaxf(fmaxf(a0, a1), fmaxf(fmaxf(a2, a3), mx));
                }
                if (pad) sum -= (float)pad * trow[pkb[pp * (PKW * 4) + c - 1]];
                r = sum * sm->inv[pp] + mx;
            }
            rbuf[lane * 17 + pp] = r;
        }
        __syncthreads();
    }

    // final pass's results
    {
        const float* rs = sm->res[(NPASS - 1) & 1];
        const int chb = (NPASS - 1) * CH_PASS;
        #pragma unroll
        for (int k = 0; k < 2; k++) {
            int chl = (tid >> 4) + 16 * k;
            int pp  = tid & 15;
            out[(((size_t)n_i * C_ + (chb + chl)) * S_ + s_i) * P_ + pp]
                = rs[chl * 17 + pp];
        }
    }
}

extern "C" void kernel_launch(void* const* d_in, const int* in_sizes, int n_in,
                              void* d_out, int out_size)
{
    const float* x    = (const float*)d_in[0];
    const int*   lbls = (const int*)d_in[1];
    float*       out  = (float*)d_out;

    cudaFuncSetAttribute(hpp_kernel, cudaFuncAttributeMaxDynamicSharedMemorySize,
                         (int)sizeof(SM));
    hpp_kernel<<<NS_, THREADS, sizeof(SM)>>>(x, lbls, out);
}